// round 6
// baseline (speedup 1.0000x reference)
#include <cuda_runtime.h>
#include <cstdint>

typedef unsigned long long ull;

// ---------------------------------------------------------------------------
// Device scratch: featuremap interleaved (H, W, C) as float4 per pixel. 4 MB.
// ---------------------------------------------------------------------------
__device__ float4 g_fmI[512 * 512];

__global__ void fm_interleave_kernel(const float* __restrict__ fm) {
    int i = blockIdx.x * blockDim.x + threadIdx.x;   // pixel index 0..262143
    if (i < 512 * 512) {
        g_fmI[i] = make_float4(fm[i],
                               fm[i + 262144],
                               fm[i + 2 * 262144],
                               fm[i + 3 * 262144]);
    }
}

// ---------------------------------------------------------------------------
// f32x2 packed helpers
// ---------------------------------------------------------------------------
__device__ __forceinline__ ull pack2(float lo, float hi) {
    ull r;
    asm("mov.b64 %0, {%1, %2};" : "=l"(r) : "f"(lo), "f"(hi));
    return r;
}
__device__ __forceinline__ void unpack2(ull v, float& lo, float& hi) {
    asm("mov.b64 {%0, %1}, %2;" : "=f"(lo), "=f"(hi) : "l"(v));
}
__device__ __forceinline__ ull ffma2(ull a, ull b, ull c) {
    ull d;
    asm("fma.rn.f32x2 %0, %1, %2, %3;" : "=l"(d) : "l"(a), "l"(b), "l"(c));
    return d;
}
__device__ __forceinline__ ull relu2(ull v) {
    float lo, hi;
    unpack2(v, lo, hi);
    lo = fmaxf(lo, 0.0f);
    hi = fmaxf(hi, 0.0f);
    return pack2(lo, hi);
}

// ---------------------------------------------------------------------------
// Bilinear sample with border clamp, matching the reference math.
// fx = clip(u*512 - 0.5, 0, 511) (algebraically identical to ref formula).
// ---------------------------------------------------------------------------
__device__ __forceinline__ void sample_fm(float u, float v, float f[4]) {
    float fx = fminf(fmaxf(fmaf(u, 512.0f, -0.5f), 0.0f), 511.0f);
    float fy = fminf(fmaxf(fmaf(v, 512.0f, -0.5f), 0.0f), 511.0f);
    float x0f = floorf(fx), y0f = floorf(fy);
    float wx = fx - x0f, wy = fy - y0f;
    int ix0 = (int)x0f, iy0 = (int)y0f;
    int ix1 = min(ix0 + 1, 511);
    int iy1 = min(iy0 + 1, 511);

    const float4* fmI = g_fmI;
    float4 v00 = __ldg(&fmI[iy0 * 512 + ix0]);
    float4 v01 = __ldg(&fmI[iy0 * 512 + ix1]);
    float4 v10 = __ldg(&fmI[iy1 * 512 + ix0]);
    float4 v11 = __ldg(&fmI[iy1 * 512 + ix1]);

    float w00 = (1.0f - wy) * (1.0f - wx);
    float w01 = (1.0f - wy) * wx;
    float w10 = wy * (1.0f - wx);
    float w11 = wy * wx;

    f[0] = v00.x * w00 + v01.x * w01 + v10.x * w10 + v11.x * w11;
    f[1] = v00.y * w00 + v01.y * w01 + v10.y * w10 + v11.y * w11;
    f[2] = v00.z * w00 + v01.z * w01 + v10.z * w10 + v11.z * w11;
    f[3] = v00.w * w00 + v01.w * w01 + v10.w * w10 + v11.w * w11;
}

// ---------------------------------------------------------------------------
// One hidden layer (NJ = 16 outputs), 2 point-pairs (= 4 points) per thread.
// Weights pre-packed {w,w}; LDS.128 fetches two adjacent packed weights.
// ---------------------------------------------------------------------------
template <int NK>
__device__ __forceinline__ void layer16(const ull* __restrict__ sW,
                                        const ull* __restrict__ sB,
                                        const ull* __restrict__ i0,
                                        const ull* __restrict__ i1,
                                        ull* __restrict__ o0,
                                        ull* __restrict__ o1) {
#pragma unroll
    for (int j = 0; j < 16; j += 2) {
        ull a0 = sB[j], a1 = sB[j];
        ull c0 = sB[j + 1], c1 = sB[j + 1];
#pragma unroll
        for (int k = 0; k < NK; k++) {
            ulonglong2 w = *reinterpret_cast<const ulonglong2*>(&sW[k * 16 + j]);
            a0 = ffma2(i0[k], w.x, a0);
            a1 = ffma2(i1[k], w.x, a1);
            c0 = ffma2(i0[k], w.y, c0);
            c1 = ffma2(i1[k], w.y, c1);
        }
        o0[j]     = relu2(a0);
        o1[j]     = relu2(a1);
        o0[j + 1] = relu2(c0);
        o1[j + 1] = relu2(c1);
    }
}

__device__ __forceinline__ void layer_out(const ull* __restrict__ sW,
                                          const ull* __restrict__ sB,
                                          const ull* __restrict__ i0,
                                          const ull* __restrict__ i1,
                                          ull o0[3], ull o1[3]) {
#pragma unroll
    for (int j = 0; j < 3; j++) {
        ull a0 = sB[j], a1 = sB[j];
#pragma unroll
        for (int k = 0; k < 16; k++) {
            ull w = sW[k * 3 + j];
            a0 = ffma2(i0[k], w, a0);
            a1 = ffma2(i1[k], w, a1);
        }
        o0[j] = a0;
        o1[j] = a1;
    }
}

// ---------------------------------------------------------------------------
// Main fused kernel: 4 points per thread (2 f32x2 pairs).
// ---------------------------------------------------------------------------
__global__ __launch_bounds__(128) void mlp_kernel(
    const float* __restrict__ x,
    const float* __restrict__ W1, const float* __restrict__ b1,
    const float* __restrict__ W2, const float* __restrict__ b2,
    const float* __restrict__ W3, const float* __restrict__ b3,
    const float* __restrict__ W4, const float* __restrict__ b4,
    const float* __restrict__ W5, const float* __restrict__ b5,
    float* __restrict__ out, int n)
{
    __shared__ alignas(16) ull sW1[7 * 16];
    __shared__ alignas(16) ull sW2[16 * 16];
    __shared__ alignas(16) ull sW3[16 * 16];
    __shared__ alignas(16) ull sW4[16 * 16];
    __shared__ alignas(16) ull sW5[16 * 3];
    __shared__ alignas(16) ull sB1[16], sB2[16], sB3[16], sB4[16], sB5[4];

    int tid = threadIdx.x;
    for (int i = tid; i < 112; i += 128) sW1[i] = pack2(W1[i], W1[i]);
    for (int i = tid; i < 256; i += 128) {
        sW2[i] = pack2(W2[i], W2[i]);
        sW3[i] = pack2(W3[i], W3[i]);
        sW4[i] = pack2(W4[i], W4[i]);
    }
    for (int i = tid; i < 48; i += 128) sW5[i] = pack2(W5[i], W5[i]);
    if (tid < 16) {
        sB1[tid] = pack2(b1[tid], b1[tid]);
        sB2[tid] = pack2(b2[tid], b2[tid]);
        sB3[tid] = pack2(b3[tid], b3[tid]);
        sB4[tid] = pack2(b4[tid], b4[tid]);
    }
    if (tid < 3) sB5[tid] = pack2(b5[tid], b5[tid]);
    __syncthreads();

    long base = (long)(blockIdx.x * 128 + tid) * 4;
    if (base >= n) return;

    // ---- load 4 points' coordinates (12 floats) ----
    float px[4], py[4], pz[4];
    if (base + 4 <= (long)n) {
        const float4* xv = reinterpret_cast<const float4*>(x + base * 3);
        float4 A = __ldg(xv), B = __ldg(xv + 1), C = __ldg(xv + 2);
        px[0] = A.x; py[0] = A.y; pz[0] = A.z;
        px[1] = A.w; py[1] = B.x; pz[1] = B.y;
        px[2] = B.z; py[2] = B.w; pz[2] = C.x;
        px[3] = C.y; py[3] = C.z; pz[3] = C.w;
    } else {
        // safe scalar tail (n not multiple of 4)
        float tmp[12];
        int cnt = (int)(n - base) * 3;
#pragma unroll
        for (int i = 0; i < 12; i++) tmp[i] = (i < cnt) ? x[base * 3 + i] : 0.0f;
#pragma unroll
        for (int p = 0; p < 4; p++) {
            px[p] = tmp[p * 3 + 0];
            py[p] = tmp[p * 3 + 1];
            pz[p] = tmp[p * 3 + 2];
        }
    }

    // ---- bilinear gather ----
    float ft[4][4];
#pragma unroll
    for (int p = 0; p < 4; p++) sample_fm(px[p], py[p], ft[p]);

    // ---- pack into 2 pairs: lane0 = even point, lane1 = odd point ----
    ull u0[16], u1[16], v0[16], v1[16];
    u0[0] = pack2(px[0], px[1]);  u1[0] = pack2(px[2], px[3]);
    u0[1] = pack2(py[0], py[1]);  u1[1] = pack2(py[2], py[3]);
    u0[2] = pack2(pz[0], pz[1]);  u1[2] = pack2(pz[2], pz[3]);
#pragma unroll
    for (int c = 0; c < 4; c++) {
        u0[3 + c] = pack2(ft[0][c], ft[1][c]);
        u1[3 + c] = pack2(ft[2][c], ft[3][c]);
    }

    // ---- MLP ----
    layer16<7>(sW1, sB1, u0, u1, v0, v1);
    layer16<16>(sW2, sB2, v0, v1, u0, u1);
    layer16<16>(sW3, sB3, u0, u1, v0, v1);
    layer16<16>(sW4, sB4, v0, v1, u0, u1);

    ull o0[3], o1[3];
    layer_out(sW5, sB5, u0, u1, o0, o1);

    // ---- unpack + store 12 floats ----
    float r[12];
    unpack2(o0[0], r[0], r[3]);
    unpack2(o0[1], r[1], r[4]);
    unpack2(o0[2], r[2], r[5]);
    unpack2(o1[0], r[6], r[9]);
    unpack2(o1[1], r[7], r[10]);
    unpack2(o1[2], r[8], r[11]);

    if (base + 4 <= (long)n) {
        float4* ov = reinterpret_cast<float4*>(out + base * 3);
        ov[0] = make_float4(r[0], r[1], r[2], r[3]);
        ov[1] = make_float4(r[4], r[5], r[6], r[7]);
        ov[2] = make_float4(r[8], r[9], r[10], r[11]);
    } else {
        int cnt = (int)(n - base) * 3;
        for (int i = 0; i < cnt; i++) out[base * 3 + i] = r[i];
    }
}

// ---------------------------------------------------------------------------
// kernel_launch — graph-capturable, allocation-free.
// Inputs: x, featuremap, W1,b1, W2,b2, W3,b3, W4,b4, W5,b5
// ---------------------------------------------------------------------------
extern "C" void kernel_launch(void* const* d_in, const int* in_sizes, int n_in,
                              void* d_out, int out_size) {
    const float* x  = (const float*)d_in[0];
    const float* fm = (const float*)d_in[1];
    const float* W1 = (const float*)d_in[2];
    const float* b1 = (const float*)d_in[3];
    const float* W2 = (const float*)d_in[4];
    const float* b2 = (const float*)d_in[5];
    const float* W3 = (const float*)d_in[6];
    const float* b3 = (const float*)d_in[7];
    const float* W4 = (const float*)d_in[8];
    const float* b4 = (const float*)d_in[9];
    const float* W5 = (const float*)d_in[10];
    const float* b5 = (const float*)d_in[11];

    int n = in_sizes[0] / 3;   // 4,000,000 points

    fm_interleave_kernel<<<(512 * 512 + 255) / 256, 256>>>(fm);

    int nthreads = (n + 3) / 4;                  // 4 points per thread
    int nblocks  = (nthreads + 127) / 128;
    mlp_kernel<<<nblocks, 128>>>(x, W1, b1, W2, b2, W3, b3, W4, b4, W5, b5,
                                 (float*)d_out, n);
}